// round 5
// baseline (speedup 1.0000x reference)
#include <cuda_runtime.h>
#include <cuda_fp16.h>

// LogicDense: out[i][j] = c0 + c1*a + c2*b + c3*a*b
//   a = x[i, idx0[j]], b = x[i, idx1[j]]
//
// R5 vs R4 (55.6 us, main kernel latency/issue-bound: all pipes <50%, issue 33%):
//  - Table fused into ONE 16-B record per column: 4 x half coeffs + 2 x u16
//    swizzled offsets -> one LDG.128 (was LDG.128 + LDG.32, two dependent loads).
//  - Column loop unrolled x2: two independent record->gather->poly chains in
//    flight (MLP against L2-hit latency ~234cyc and LDS latency).
//  - ROWS=8 fp16 tile (64 KiB, 3 blocks/SM) and swizzle unchanged.
//  - Math stays fp32; half-coeff rounding adds ~5e-5 to the norm error.

#define ROWS 8
#define MAX_OUT 16384

__device__ uint4 g_tab[MAX_OUT];   // .x=h2(c0,c1) .y=h2(c2,c3) .z=offA|offB<<16 .w=pad

__constant__ float c_T[64] = {
    0.f, 0.f, 0.f, 0.f,
    0.f, 0.f, 0.f, 1.f,
    0.f, 1.f, 0.f,-1.f,
    0.f, 1.f, 0.f, 0.f,
    0.f, 0.f, 1.f,-1.f,
    0.f, 0.f, 1.f, 0.f,
    0.f, 1.f, 1.f,-2.f,
    0.f, 1.f, 1.f,-1.f,
    1.f,-1.f,-1.f, 1.f,
    1.f,-1.f,-1.f, 2.f,
    1.f, 0.f,-1.f, 0.f,
    1.f, 0.f,-1.f, 1.f,
    1.f,-1.f, 0.f, 0.f,
    1.f,-1.f, 0.f, 1.f,
    1.f, 0.f, 0.f,-1.f,
    1.f, 0.f, 0.f, 0.f
};

__device__ __forceinline__ int swz_off(int idx) {
    // half-index of the 8-row group of element idx in the swizzled tile
    return (idx << 3) ^ (((idx >> 3) & 7) << 3);
}

__global__ void precompute_kernel(const void* __restrict__ idx_raw,
                                  const float* __restrict__ w,
                                  int out_dim) {
    __shared__ unsigned int red[128];
    __shared__ int s_is64;

    // int64-vs-int32 detection: OR of odd u32 words == 0 iff int64 high words.
    const unsigned int* u = (const unsigned int*)idx_raw;
    int n_chk = 2 * out_dim;
    if (n_chk > 512) n_chk = 512;
    unsigned int v = 0;
    for (int k = 1 + 2 * (int)threadIdx.x; k < n_chk; k += 2 * (int)blockDim.x)
        v |= u[k];
    red[threadIdx.x] = v;
    __syncthreads();
    for (int s = 64; s > 0; s >>= 1) {
        if ((int)threadIdx.x < s) red[threadIdx.x] |= red[threadIdx.x + s];
        __syncthreads();
    }
    if (threadIdx.x == 0) s_is64 = (red[0] == 0u) ? 1 : 0;
    __syncthreads();
    const int is64 = s_is64;

    int j = blockIdx.x * blockDim.x + threadIdx.x;
    if (j >= out_dim) return;

    float wv[16];
    float m = -1e30f;
#pragma unroll
    for (int k = 0; k < 16; k++) {
        wv[k] = w[j * 16 + k];
        m = fmaxf(m, wv[k]);
    }
    float s = 0.f;
#pragma unroll
    for (int k = 0; k < 16; k++) {
        wv[k] = __expf(wv[k] - m);
        s += wv[k];
    }
    float inv = 1.f / s;
    float c0 = 0.f, c1 = 0.f, c2 = 0.f, c3 = 0.f;
#pragma unroll
    for (int k = 0; k < 16; k++) {
        float p = wv[k] * inv;
        c0 = fmaf(p, c_T[4 * k + 0], c0);
        c1 = fmaf(p, c_T[4 * k + 1], c1);
        c2 = fmaf(p, c_T[4 * k + 2], c2);
        c3 = fmaf(p, c_T[4 * k + 3], c3);
    }

    int i0, i1;
    if (is64) {
        const long long* p = (const long long*)idx_raw;
        i0 = (int)p[j];
        i1 = (int)p[out_dim + j];
    } else {
        const int* p = (const int*)idx_raw;
        i0 = p[j];
        i1 = p[out_dim + j];
    }

    __half2 c01 = __floats2half2_rn(c0, c1);
    __half2 c23 = __floats2half2_rn(c2, c3);
    uint4 rec;
    rec.x = *(unsigned int*)&c01;
    rec.y = *(unsigned int*)&c23;
    rec.z = (unsigned int)swz_off(i0) | ((unsigned int)swz_off(i1) << 16);
    rec.w = 0u;
    g_tab[j] = rec;
}

__device__ __forceinline__ unsigned int pack_h2(float lo, float hi) {
    __half2 h = __floats2half2_rn(lo, hi);
    return *(unsigned int*)&h;
}

template <bool FULL>
__global__ __launch_bounds__(512, 3) void logic_main_kernel(
    const float* __restrict__ x,
    float* __restrict__ out,
    int in_dim, int out_dim, int batch) {
    extern __shared__ __half sh[];   // in_dim * 8 halfs (64 KiB @ 4096), swizzled

    const int rb = blockIdx.x * ROWS;
    const int nr = FULL ? ROWS : min(ROWS, batch - rb);

    // ---- stage 8 rows: LDG.128 x8, convert to half, repack, STS.128 x4 ----
    {
        const int n4 = in_dim >> 2;   // element-chunks of 4
        const float* xb = x + (size_t)rb * in_dim;
        for (int i = threadIdx.x; i < n4; i += blockDim.x) {
            float4 r[ROWS];
#pragma unroll
            for (int rr = 0; rr < ROWS; rr++) {
                int row = (FULL || rr < nr) ? rr : 0;
                r[rr] = *(const float4*)(xb + (size_t)row * in_dim + (i << 2));
            }
#pragma unroll
            for (int k = 0; k < 4; k++) {
                uint4 pk;
                pk.x = pack_h2((&r[0].x)[k], (&r[1].x)[k]);
                pk.y = pack_h2((&r[2].x)[k], (&r[3].x)[k]);
                pk.z = pack_h2((&r[4].x)[k], (&r[5].x)[k]);
                pk.w = pack_h2((&r[6].x)[k], (&r[7].x)[k]);
                const int idx = (i << 2) + k;
                *(uint4*)(sh + swz_off(idx)) = pk;
            }
        }
    }
    __syncthreads();

    // ---- compute: one LDG.128 record + two LDS.128 gathers serve 8 rows ----
#pragma unroll 2
    for (int j = threadIdx.x; j < out_dim; j += blockDim.x) {
        const uint4 rec = g_tab[j];

        const uint4 ap = *(const uint4*)(sh + (rec.z & 0xFFFFu));
        const uint4 bp = *(const uint4*)(sh + (rec.z >> 16));

        const float2 c01 = __half22float2(*(const __half2*)&rec.x);
        const float2 c23 = __half22float2(*(const __half2*)&rec.y);

        float2 a01 = __half22float2(*(const __half2*)&ap.x);
        float2 a23 = __half22float2(*(const __half2*)&ap.y);
        float2 a45 = __half22float2(*(const __half2*)&ap.z);
        float2 a67 = __half22float2(*(const __half2*)&ap.w);
        float2 b01 = __half22float2(*(const __half2*)&bp.x);
        float2 b23 = __half22float2(*(const __half2*)&bp.y);
        float2 b45 = __half22float2(*(const __half2*)&bp.z);
        float2 b67 = __half22float2(*(const __half2*)&bp.w);

        const float va[ROWS] = {a01.x, a01.y, a23.x, a23.y, a45.x, a45.y, a67.x, a67.y};
        const float vb[ROWS] = {b01.x, b01.y, b23.x, b23.y, b45.x, b45.y, b67.x, b67.y};

        float* op = out + (size_t)rb * out_dim + j;
#pragma unroll
        for (int r = 0; r < ROWS; r++) {
            if (FULL || r < nr) {
                // c0 + c1*a + c2*b + c3*a*b = a*(c1 + c3*b) + (c0 + c2*b)
                float res = fmaf(va[r], fmaf(vb[r], c23.y, c01.y),
                                 fmaf(vb[r], c23.x, c01.x));
                op[(size_t)r * out_dim] = res;
            }
        }
    }
}

extern "C" void kernel_launch(void* const* d_in, const int* in_sizes, int n_in,
                              void* d_out, int out_size) {
    const float* x   = (const float*)d_in[0];
    const void*  idx = d_in[1];
    const float* w   = (const float*)d_in[2];
    float*       out = (float*)d_out;

    const int out_dim = in_sizes[2] / 16;         // weight is (out_dim, 16)
    const int batch   = out_size / out_dim;       // out is (batch, out_dim)
    const int in_dim  = in_sizes[0] / batch;      // x is (batch, in_dim)

    precompute_kernel<<<(out_dim + 127) / 128, 128>>>(idx, w, out_dim);

    const size_t smem = (size_t)in_dim * ROWS * sizeof(__half);   // 64 KiB @ 4096
    const int grid = (batch + ROWS - 1) / ROWS;

    if (batch % ROWS == 0) {
        cudaFuncSetAttribute(logic_main_kernel<true>,
                             cudaFuncAttributeMaxDynamicSharedMemorySize, (int)smem);
        logic_main_kernel<true><<<grid, 512, smem>>>(x, out, in_dim, out_dim, batch);
    } else {
        cudaFuncSetAttribute(logic_main_kernel<false>,
                             cudaFuncAttributeMaxDynamicSharedMemorySize, (int)smem);
        logic_main_kernel<false><<<grid, 512, smem>>>(x, out, in_dim, out_dim, batch);
    }
}

// round 6
// speedup vs baseline: 1.2102x; 1.2102x over previous
#include <cuda_runtime.h>
#include <cuda_fp16.h>

// LogicDense: out[i][j] = c0 + c1*a + c2*b + c3*a*b
//   a = x[i, idx0[j]], b = x[i, idx1[j]]
//
// R6 vs R5 (47.7 us main, SMSP issue eaten by STG.32 issue cost ~5cyc each):
//  - Each thread handles a COLUMN PAIR -> 8 x STG.64 per 2 cols (issue 62cyc)
//    instead of 16 x STG.32 (80cyc); addressing amortized over 2 columns.
//  - Table split into tabE/tabO (even/odd cols) so lanes own adjacent columns
//    while both table loads stay unit-stride contiguous (4-wf floor each).
//  - 2 LDG.128 + 4 LDS.128 independent per iter (MLP up).
//  - No occupancy cap: ~50 regs, 2 blocks/SM, no spills.
//  - ROWS=8 fp16 tile (64 KiB) + swizzle unchanged.

#define ROWS 8
#define MAX_OUT 16384

__device__ uint4 g_tabE[MAX_OUT / 2];  // records for even columns 2p
__device__ uint4 g_tabO[MAX_OUT / 2];  // records for odd  columns 2p+1
// record: .x=h2(c0,c1) .y=h2(c2,c3) .z=offA|offB<<16 .w=pad

__constant__ float c_T[64] = {
    0.f, 0.f, 0.f, 0.f,
    0.f, 0.f, 0.f, 1.f,
    0.f, 1.f, 0.f,-1.f,
    0.f, 1.f, 0.f, 0.f,
    0.f, 0.f, 1.f,-1.f,
    0.f, 0.f, 1.f, 0.f,
    0.f, 1.f, 1.f,-2.f,
    0.f, 1.f, 1.f,-1.f,
    1.f,-1.f,-1.f, 1.f,
    1.f,-1.f,-1.f, 2.f,
    1.f, 0.f,-1.f, 0.f,
    1.f, 0.f,-1.f, 1.f,
    1.f,-1.f, 0.f, 0.f,
    1.f,-1.f, 0.f, 1.f,
    1.f, 0.f, 0.f,-1.f,
    1.f, 0.f, 0.f, 0.f
};

__device__ __forceinline__ int swz_off(int idx) {
    // half-index of the 8-row group of element idx in the swizzled tile
    return (idx << 3) ^ (((idx >> 3) & 7) << 3);
}

__global__ void precompute_kernel(const void* __restrict__ idx_raw,
                                  const float* __restrict__ w,
                                  int out_dim) {
    __shared__ unsigned int red[128];
    __shared__ int s_is64;

    // int64-vs-int32 detection: OR of odd u32 words == 0 iff int64 high words.
    const unsigned int* u = (const unsigned int*)idx_raw;
    int n_chk = 2 * out_dim;
    if (n_chk > 512) n_chk = 512;
    unsigned int v = 0;
    for (int k = 1 + 2 * (int)threadIdx.x; k < n_chk; k += 2 * (int)blockDim.x)
        v |= u[k];
    red[threadIdx.x] = v;
    __syncthreads();
    for (int s = 64; s > 0; s >>= 1) {
        if ((int)threadIdx.x < s) red[threadIdx.x] |= red[threadIdx.x + s];
        __syncthreads();
    }
    if (threadIdx.x == 0) s_is64 = (red[0] == 0u) ? 1 : 0;
    __syncthreads();
    const int is64 = s_is64;

    int j = blockIdx.x * blockDim.x + threadIdx.x;
    if (j >= out_dim) return;

    float wv[16];
    float m = -1e30f;
#pragma unroll
    for (int k = 0; k < 16; k++) {
        wv[k] = w[j * 16 + k];
        m = fmaxf(m, wv[k]);
    }
    float s = 0.f;
#pragma unroll
    for (int k = 0; k < 16; k++) {
        wv[k] = __expf(wv[k] - m);
        s += wv[k];
    }
    float inv = 1.f / s;
    float c0 = 0.f, c1 = 0.f, c2 = 0.f, c3 = 0.f;
#pragma unroll
    for (int k = 0; k < 16; k++) {
        float p = wv[k] * inv;
        c0 = fmaf(p, c_T[4 * k + 0], c0);
        c1 = fmaf(p, c_T[4 * k + 1], c1);
        c2 = fmaf(p, c_T[4 * k + 2], c2);
        c3 = fmaf(p, c_T[4 * k + 3], c3);
    }

    int i0, i1;
    if (is64) {
        const long long* p = (const long long*)idx_raw;
        i0 = (int)p[j];
        i1 = (int)p[out_dim + j];
    } else {
        const int* p = (const int*)idx_raw;
        i0 = p[j];
        i1 = p[out_dim + j];
    }

    __half2 c01 = __floats2half2_rn(c0, c1);
    __half2 c23 = __floats2half2_rn(c2, c3);
    uint4 rec;
    rec.x = *(unsigned int*)&c01;
    rec.y = *(unsigned int*)&c23;
    rec.z = (unsigned int)swz_off(i0) | ((unsigned int)swz_off(i1) << 16);
    rec.w = 0u;
    if (j & 1) g_tabO[j >> 1] = rec;
    else       g_tabE[j >> 1] = rec;
}

__device__ __forceinline__ unsigned int pack_h2(float lo, float hi) {
    __half2 h = __floats2half2_rn(lo, hi);
    return *(unsigned int*)&h;
}

__device__ __forceinline__ float2 h22f2(unsigned int u) {
    return __half22float2(*(const __half2*)&u);
}

template <bool FULL>
__global__ __launch_bounds__(512) void logic_main_kernel(
    const float* __restrict__ x,
    float* __restrict__ out,
    int in_dim, int out_dim, int batch) {
    extern __shared__ __half sh[];   // in_dim * 8 halfs (64 KiB @ 4096), swizzled

    const int rb = blockIdx.x * ROWS;
    const int nr = FULL ? ROWS : min(ROWS, batch - rb);

    // ---- stage 8 rows: LDG.128 x8, convert to half, repack, STS.128 x4 ----
    {
        const int n4 = in_dim >> 2;   // element-chunks of 4
        const float* xb = x + (size_t)rb * in_dim;
        for (int i = threadIdx.x; i < n4; i += blockDim.x) {
            float4 r[ROWS];
#pragma unroll
            for (int rr = 0; rr < ROWS; rr++) {
                int row = (FULL || rr < nr) ? rr : 0;
                r[rr] = *(const float4*)(xb + (size_t)row * in_dim + (i << 2));
            }
#pragma unroll
            for (int k = 0; k < 4; k++) {
                uint4 pk;
                pk.x = pack_h2((&r[0].x)[k], (&r[1].x)[k]);
                pk.y = pack_h2((&r[2].x)[k], (&r[3].x)[k]);
                pk.z = pack_h2((&r[4].x)[k], (&r[5].x)[k]);
                pk.w = pack_h2((&r[6].x)[k], (&r[7].x)[k]);
                const int idx = (i << 2) + k;
                *(uint4*)(sh + swz_off(idx)) = pk;
            }
        }
    }
    __syncthreads();

    // ---- compute: column pair per thread, STG.64 stores ----
    const int npair = out_dim >> 1;
    for (int q = threadIdx.x; q < npair; q += blockDim.x) {
        const uint4 rE = g_tabE[q];
        const uint4 rO = g_tabO[q];

        const uint4 aE = *(const uint4*)(sh + (rE.z & 0xFFFFu));
        const uint4 bE = *(const uint4*)(sh + (rE.z >> 16));
        const uint4 aO = *(const uint4*)(sh + (rO.z & 0xFFFFu));
        const uint4 bO = *(const uint4*)(sh + (rO.z >> 16));

        const float2 cE01 = h22f2(rE.x);
        const float2 cE23 = h22f2(rE.y);
        const float2 cO01 = h22f2(rO.x);
        const float2 cO23 = h22f2(rO.y);

        float* op = out + (size_t)rb * out_dim + 2 * q;
#pragma unroll
        for (int r2 = 0; r2 < 4; r2++) {
            const float2 vaE = h22f2((&aE.x)[r2]);
            const float2 vbE = h22f2((&bE.x)[r2]);
            const float2 vaO = h22f2((&aO.x)[r2]);
            const float2 vbO = h22f2((&bO.x)[r2]);

            // row 2*r2
            if (FULL || 2 * r2 < nr) {
                float2 res;
                res.x = fmaf(vaE.x, fmaf(vbE.x, cE23.y, cE01.y),
                             fmaf(vbE.x, cE23.x, cE01.x));
                res.y = fmaf(vaO.x, fmaf(vbO.x, cO23.y, cO01.y),
                             fmaf(vbO.x, cO23.x, cO01.x));
                *(float2*)(op + (size_t)(2 * r2) * out_dim) = res;
            }
            // row 2*r2+1
            if (FULL || 2 * r2 + 1 < nr) {
                float2 res;
                res.x = fmaf(vaE.y, fmaf(vbE.y, cE23.y, cE01.y),
                             fmaf(vbE.y, cE23.x, cE01.x));
                res.y = fmaf(vaO.y, fmaf(vbO.y, cO23.y, cO01.y),
                             fmaf(vbO.y, cO23.x, cO01.x));
                *(float2*)(op + (size_t)(2 * r2 + 1) * out_dim) = res;
            }
        }
    }
}

extern "C" void kernel_launch(void* const* d_in, const int* in_sizes, int n_in,
                              void* d_out, int out_size) {
    const float* x   = (const float*)d_in[0];
    const void*  idx = d_in[1];
    const float* w   = (const float*)d_in[2];
    float*       out = (float*)d_out;

    const int out_dim = in_sizes[2] / 16;         // weight is (out_dim, 16)
    const int batch   = out_size / out_dim;       // out is (batch, out_dim)
    const int in_dim  = in_sizes[0] / batch;      // x is (batch, in_dim)

    precompute_kernel<<<(out_dim + 127) / 128, 128>>>(idx, w, out_dim);

    const size_t smem = (size_t)in_dim * ROWS * sizeof(__half);   // 64 KiB @ 4096
    const int grid = (batch + ROWS - 1) / ROWS;

    if (batch % ROWS == 0) {
        cudaFuncSetAttribute(logic_main_kernel<true>,
                             cudaFuncAttributeMaxDynamicSharedMemorySize, (int)smem);
        logic_main_kernel<true><<<grid, 512, smem>>>(x, out, in_dim, out_dim, batch);
    } else {
        cudaFuncSetAttribute(logic_main_kernel<false>,
                             cudaFuncAttributeMaxDynamicSharedMemorySize, (int)smem);
        logic_main_kernel<false><<<grid, 512, smem>>>(x, out, in_dim, out_dim, batch);
    }
}